// round 3
// baseline (speedup 1.0000x reference)
#include <cuda_runtime.h>
#include <cuda_bf16.h>

#define SENSOR   256
#define IMG_W    1024
#define IMG_H    1024
#define SPP      16
#define NCH      3
#define NBATCH   4
#define HW       (IMG_H * IMG_W)

__global__ __launch_bounds__(256, 5)
void foveated_sensor_kernel(const float* __restrict__ img,
                            const float* __restrict__ t,
                            const float* __restrict__ jitter,
                            float* __restrict__ out)
{
    const int p  = blockIdx.x * 256 + threadIdx.x;   // sensor pixel 0..65535
    const int b  = blockIdx.y;                        // batch 0..3
    const int sw = p & (SENSOR - 1);
    const int sh = p >> 8;

    const float step = 2.0f / (float)SENSOR;
    const float pxv = -1.0f + (float)sw * step;
    const float pyv = -1.0f + (float)sh * step;

    const float tt    = __ldg(t);
    const float s     = tanhf(tt);
    const float inv_s = 1.0f / s;

    const float* __restrict__ imgb = img + (size_t)b * NCH * HW;
    const float2* __restrict__ jit = (const float2*)jitter;

    float acc0 = 0.f, acc1 = 0.f, acc2 = 0.f, dsum = 0.f;

#pragma unroll 2
    for (int k = 0; k < SPP; ++k) {
        float2 j = __ldg(&jit[(k << 16) + p]);
        float posx = pxv + j.x * step;
        float posy = pyv + j.y * step;

        float thx = tanhf(tt * posx);
        float thy = tanhf(tt * posy);

        float ddx = tt * (1.0f - thx * thx) * inv_s;
        float ddy = tt * (1.0f - thy * thy) * inv_s;
        float det = ddx * ddy;
        dsum += det;

        float gx = (thx * inv_s + 1.0f) * (0.5f * IMG_W) - 0.5f;
        float gy = (thy * inv_s + 1.0f) * (0.5f * IMG_H) - 0.5f;
        gx = fminf(fmaxf(gx, 0.0f), (float)(IMG_W - 1));
        gy = fminf(fmaxf(gy, 0.0f), (float)(IMG_H - 1));

        float x0f = floorf(gx);
        float y0f = floorf(gy);
        float wx = gx - x0f;
        float wy = gy - y0f;

        int x0 = (int)x0f;
        int y0 = (int)y0f;
        int y1 = min(y0 + 1, IMG_H - 1);

        const int frac = x0 & 3;
        const int xb   = x0 & ~3;
        const bool f1  = (frac & 1) != 0;
        const bool f2  = (frac & 2) != 0;
        const bool extra = (frac == 3) && (x0 < IMG_W - 1);

        const int r0 = (y0 << 10) + xb;
        const int r1 = (y1 << 10) + xb;

        // ---- channel 0 ----
        {
            const float* ip = imgb;
            float4 a0 = __ldg((const float4*)(ip + r0));
            float4 a1 = __ldg((const float4*)(ip + r1));
            float e0 = a0.w, e1 = a1.w;
            if (extra) { e0 = __ldg(ip + r0 + 4); e1 = __ldg(ip + r1 + 4); }
            float v00 = f2 ? (f1 ? a0.w : a0.z) : (f1 ? a0.y : a0.x);
            float v01 = f2 ? (f1 ? e0   : a0.w) : (f1 ? a0.z : a0.y);
            float v10 = f2 ? (f1 ? a1.w : a1.z) : (f1 ? a1.y : a1.x);
            float v11 = f2 ? (f1 ? e1   : a1.w) : (f1 ? a1.z : a1.y);
            float top = fmaf(wx, v01 - v00, v00);
            float bot = fmaf(wx, v11 - v10, v10);
            acc0 = fmaf(fmaf(wy, bot - top, top), det, acc0);
        }
        // ---- channel 1 ----
        {
            const float* ip = imgb + HW;
            float4 a0 = __ldg((const float4*)(ip + r0));
            float4 a1 = __ldg((const float4*)(ip + r1));
            float e0 = a0.w, e1 = a1.w;
            if (extra) { e0 = __ldg(ip + r0 + 4); e1 = __ldg(ip + r1 + 4); }
            float v00 = f2 ? (f1 ? a0.w : a0.z) : (f1 ? a0.y : a0.x);
            float v01 = f2 ? (f1 ? e0   : a0.w) : (f1 ? a0.z : a0.y);
            float v10 = f2 ? (f1 ? a1.w : a1.z) : (f1 ? a1.y : a1.x);
            float v11 = f2 ? (f1 ? e1   : a1.w) : (f1 ? a1.z : a1.y);
            float top = fmaf(wx, v01 - v00, v00);
            float bot = fmaf(wx, v11 - v10, v10);
            acc1 = fmaf(fmaf(wy, bot - top, top), det, acc1);
        }
        // ---- channel 2 ----
        {
            const float* ip = imgb + 2 * HW;
            float4 a0 = __ldg((const float4*)(ip + r0));
            float4 a1 = __ldg((const float4*)(ip + r1));
            float e0 = a0.w, e1 = a1.w;
            if (extra) { e0 = __ldg(ip + r0 + 4); e1 = __ldg(ip + r1 + 4); }
            float v00 = f2 ? (f1 ? a0.w : a0.z) : (f1 ? a0.y : a0.x);
            float v01 = f2 ? (f1 ? e0   : a0.w) : (f1 ? a0.z : a0.y);
            float v10 = f2 ? (f1 ? a1.w : a1.z) : (f1 ? a1.y : a1.x);
            float v11 = f2 ? (f1 ? e1   : a1.w) : (f1 ? a1.z : a1.y);
            float top = fmaf(wx, v01 - v00, v00);
            float bot = fmaf(wx, v11 - v10, v10);
            acc2 = fmaf(fmaf(wy, bot - top, top), det, acc2);
        }
    }

    const float invd = 1.0f / dsum;
    out[((b * NCH + 0) << 16) + p] = acc0 * invd;
    out[((b * NCH + 1) << 16) + p] = acc1 * invd;
    out[((b * NCH + 2) << 16) + p] = acc2 * invd;
}

extern "C" void kernel_launch(void* const* d_in, const int* in_sizes, int n_in,
                              void* d_out, int out_size)
{
    const float* img    = (const float*)d_in[0];
    const float* t      = (const float*)d_in[1];
    const float* jitter = (const float*)d_in[2];
    float* out          = (float*)d_out;

    dim3 grid(SENSOR * SENSOR / 256, NBATCH);
    foveated_sensor_kernel<<<grid, 256>>>(img, t, jitter, out);
}

// round 4
// speedup vs baseline: 1.1271x; 1.1271x over previous
#include <cuda_runtime.h>
#include <cuda_bf16.h>

#define SENSOR   256
#define IMG_W    1024
#define IMG_H    1024
#define SPP      16
#define NCH      3
#define NBATCH   4
#define HW       (IMG_H * IMG_W)

// fast exact-enough tanh: 1 - 2/(exp(2x)+1).  __expf error ~few ulp -> gx error << 1e-2 px.
__device__ __forceinline__ float ftanh(float x) {
    float e = __expf(2.0f * x);
    return 1.0f - __fdividef(2.0f, e + 1.0f);
}

__global__ __launch_bounds__(128, 4)
void foveated_sensor_kernel(const float* __restrict__ img,
                            const float* __restrict__ t,
                            const float* __restrict__ jitter,
                            float* __restrict__ out)
{
    const int p  = blockIdx.x * 128 + threadIdx.x;   // sensor pixel 0..65535
    const int sw = p & (SENSOR - 1);
    const int sh = p >> 8;

    const float step = 2.0f / (float)SENSOR;
    const float pxv = -1.0f + (float)sw * step;
    const float pyv = -1.0f + (float)sh * step;

    const float tt    = __ldg(t);
    const float s     = tanhf(tt);
    const float inv_s = 1.0f / s;

    const float2* __restrict__ jit = (const float2*)jitter;

    // accumulators: 4 batches x 3 channels + det sum
    float acc[NBATCH][NCH];
#pragma unroll
    for (int b = 0; b < NBATCH; ++b)
#pragma unroll
        for (int c = 0; c < NCH; ++c) acc[b][c] = 0.f;
    float dsum = 0.f;

    for (int k = 0; k < SPP; ++k) {
        float2 j = __ldg(&jit[(k << 16) + p]);
        float posx = pxv + j.x * step;
        float posy = pyv + j.y * step;

        float thx = ftanh(tt * posx);
        float thy = ftanh(tt * posy);

        float ddx = tt * (1.0f - thx * thx) * inv_s;
        float ddy = tt * (1.0f - thy * thy) * inv_s;
        float det = ddx * ddy;
        dsum += det;

        float gx = (thx * inv_s + 1.0f) * (0.5f * IMG_W) - 0.5f;
        float gy = (thy * inv_s + 1.0f) * (0.5f * IMG_H) - 0.5f;
        gx = fminf(fmaxf(gx, 0.0f), (float)(IMG_W - 1));
        gy = fminf(fmaxf(gy, 0.0f), (float)(IMG_H - 1));

        float x0f = floorf(gx);
        float y0f = floorf(gy);
        float wx = gx - x0f;
        float wy = gy - y0f;

        int x0 = (int)x0f;
        int y0 = (int)y0f;
        int x1 = min(x0 + 1, IMG_W - 1);
        int y1 = min(y0 + 1, IMG_H - 1);

        const int o00 = (y0 << 10) + x0;
        const int o01 = (y0 << 10) + x1;
        const int o10 = (y1 << 10) + x0;
        const int o11 = (y1 << 10) + x1;

#pragma unroll
        for (int b = 0; b < NBATCH; ++b) {
#pragma unroll
            for (int c = 0; c < NCH; ++c) {
                const float* ip = img + (size_t)(b * NCH + c) * HW;
                float v00 = __ldg(ip + o00);
                float v01 = __ldg(ip + o01);
                float v10 = __ldg(ip + o10);
                float v11 = __ldg(ip + o11);
                float top = fmaf(wx, v01 - v00, v00);
                float bot = fmaf(wx, v11 - v10, v10);
                acc[b][c] = fmaf(fmaf(wy, bot - top, top), det, acc[b][c]);
            }
        }
    }

    const float invd = 1.0f / dsum;
#pragma unroll
    for (int b = 0; b < NBATCH; ++b)
#pragma unroll
        for (int c = 0; c < NCH; ++c)
            out[((b * NCH + c) << 16) + p] = acc[b][c] * invd;
}

extern "C" void kernel_launch(void* const* d_in, const int* in_sizes, int n_in,
                              void* d_out, int out_size)
{
    const float* img    = (const float*)d_in[0];
    const float* t      = (const float*)d_in[1];
    const float* jitter = (const float*)d_in[2];
    float* out          = (float*)d_out;

    foveated_sensor_kernel<<<SENSOR * SENSOR / 128, 128>>>(img, t, jitter, out);
}

// round 5
// speedup vs baseline: 1.6075x; 1.4263x over previous
#include <cuda_runtime.h>
#include <cuda_bf16.h>

#define SENSOR   256
#define IMG_W    1024
#define IMG_H    1024
#define SPP      16
#define NCH      3
#define NBATCH   4
#define HW       (IMG_H * IMG_W)

// fast tanh: 1 - 2/(exp(2x)+1); __expf error few-ulp -> position error << 1e-2 px
__device__ __forceinline__ float ftanh(float x) {
    float e = __expf(2.0f * x);
    return 1.0f - __fdividef(2.0f, e + 1.0f);
}

__global__ __launch_bounds__(256, 5)
void foveated_sensor_kernel(const float* __restrict__ img,
                            const float* __restrict__ t,
                            const float* __restrict__ jitter,
                            float* __restrict__ out)
{
    const int p  = blockIdx.x * 256 + threadIdx.x;   // sensor pixel 0..65535
    const int b  = blockIdx.y;                        // batch 0..3
    const int sw = p & (SENSOR - 1);
    const int sh = p >> 8;

    const float step = 2.0f / (float)SENSOR;
    const float pxv = -1.0f + (float)sw * step;
    const float pyv = -1.0f + (float)sh * step;

    const float tt    = __ldg(t);
    const float s     = tanhf(tt);          // once per thread, full precision
    const float inv_s = 1.0f / s;

    const float* __restrict__ imgb = img + (size_t)b * NCH * HW;
    const float2* __restrict__ jit = (const float2*)jitter;

    float acc0 = 0.f, acc1 = 0.f, acc2 = 0.f, dsum = 0.f;

#pragma unroll 4
    for (int k = 0; k < SPP; ++k) {
        float2 j = __ldg(&jit[(k << 16) + p]);
        float posx = pxv + j.x * step;
        float posy = pyv + j.y * step;

        float thx = ftanh(tt * posx);
        float thy = ftanh(tt * posy);

        float ddx = tt * (1.0f - thx * thx) * inv_s;
        float ddy = tt * (1.0f - thy * thy) * inv_s;
        float det = ddx * ddy;
        dsum += det;

        float gx = (thx * inv_s + 1.0f) * (0.5f * IMG_W) - 0.5f;
        float gy = (thy * inv_s + 1.0f) * (0.5f * IMG_H) - 0.5f;
        gx = fminf(fmaxf(gx, 0.0f), (float)(IMG_W - 1));
        gy = fminf(fmaxf(gy, 0.0f), (float)(IMG_H - 1));

        float x0f = floorf(gx);
        float y0f = floorf(gy);
        float wx = gx - x0f;
        float wy = gy - y0f;

        int x0 = (int)x0f;
        int y0 = (int)y0f;
        int x1 = min(x0 + 1, IMG_W - 1);
        int y1 = min(y0 + 1, IMG_H - 1);

        const int o00 = (y0 << 10) + x0;
        const int o01 = (y0 << 10) + x1;
        const int o10 = (y1 << 10) + x0;
        const int o11 = (y1 << 10) + x1;

        // channel 0
        float a00 = __ldg(imgb + o00);
        float a01 = __ldg(imgb + o01);
        float a10 = __ldg(imgb + o10);
        float a11 = __ldg(imgb + o11);
        // channel 1
        const float* ip1 = imgb + HW;
        float b00 = __ldg(ip1 + o00);
        float b01 = __ldg(ip1 + o01);
        float b10 = __ldg(ip1 + o10);
        float b11 = __ldg(ip1 + o11);
        // channel 2
        const float* ip2 = imgb + 2 * HW;
        float c00 = __ldg(ip2 + o00);
        float c01 = __ldg(ip2 + o01);
        float c10 = __ldg(ip2 + o10);
        float c11 = __ldg(ip2 + o11);

        float topa = fmaf(wx, a01 - a00, a00);
        float bota = fmaf(wx, a11 - a10, a10);
        acc0 = fmaf(fmaf(wy, bota - topa, topa), det, acc0);

        float topb = fmaf(wx, b01 - b00, b00);
        float botb = fmaf(wx, b11 - b10, b10);
        acc1 = fmaf(fmaf(wy, botb - topb, topb), det, acc1);

        float topc = fmaf(wx, c01 - c00, c00);
        float botc = fmaf(wx, c11 - c10, c10);
        acc2 = fmaf(fmaf(wy, botc - topc, topc), det, acc2);
    }

    const float invd = 1.0f / dsum;
    out[((b * NCH + 0) << 16) + p] = acc0 * invd;
    out[((b * NCH + 1) << 16) + p] = acc1 * invd;
    out[((b * NCH + 2) << 16) + p] = acc2 * invd;
}

extern "C" void kernel_launch(void* const* d_in, const int* in_sizes, int n_in,
                              void* d_out, int out_size)
{
    const float* img    = (const float*)d_in[0];
    const float* t      = (const float*)d_in[1];
    const float* jitter = (const float*)d_in[2];
    float* out          = (float*)d_out;

    dim3 grid(SENSOR * SENSOR / 256, NBATCH);
    foveated_sensor_kernel<<<grid, 256>>>(img, t, jitter, out);
}